// round 16
// baseline (speedup 1.0000x reference)
#include <cuda_runtime.h>

// out_b = Wp (s_b ∘ (Wq X_b)) + X_b,  s_b[c] = sum_n (Wk X_b)[c,n]*(Wv X_b)[c,n]
// B=2, C=64, N=1024. 128 blocks x 256 threads, one wave, ONE grid barrier.
// Thread tile: 2 channels x 2 columns. Packed fma.rn.f32x2 inner products.
// Barrier: atomic-free, release-free. Each block stores epoch to its own slot;
// EVERY block polls all 128 slots directly (no central release hop).
// Replay-safe: every launch increments every slot exactly once, so all slots
// are equal at launch start; each block reads its own slot to learn the epoch.

#define NBLK 128
#define NTHR 256
#define WS 68
#define XS 68

#define OFF_WK 0
#define OFF_WV (64 * WS)
#define OFF_WQ (2 * 64 * WS)
#define OFF_WP (3 * 64 * WS)
#define OFF_XT (4 * 64 * WS)
#define OFF_YS (OFF_XT + 16 * XS)
#define OFF_SS (OFF_YS + 16 * XS)
#define SMEM_FLOATS (OFF_SS + 64)

typedef unsigned long long u64;

__device__ float g_sPart[2][64][64];

// Per-block arrival slots (monotonic; zero-initialized at module load).
__device__ volatile unsigned g_arrive[NBLK];

__device__ __forceinline__ void fma2(u64& d, u64 a, u64 b) {
    asm("fma.rn.f32x2 %0, %1, %2, %0;" : "+l"(d) : "l"(a), "l"(b));
}
__device__ __forceinline__ u64 mul2(u64 a, u64 b) {
    u64 d;
    asm("mul.rn.f32x2 %0, %1, %2;" : "=l"(d) : "l"(a), "l"(b));
    return d;
}
__device__ __forceinline__ float hsum2(u64 v) {
    float lo, hi;
    asm("mov.b64 {%0, %1}, %2;" : "=f"(lo), "=f"(hi) : "l"(v));
    return lo + hi;
}

extern __shared__ float sm[];

__global__ void __launch_bounds__(NTHR) attn_fused(
    const float* __restrict__ x,
    const float* __restrict__ wq, const float* __restrict__ wk,
    const float* __restrict__ wv, const float* __restrict__ wp,
    float* __restrict__ out)
{
    __shared__ unsigned sEpoch;

    const int tid = threadIdx.x;
    const int blk = blockIdx.x;
    const int b   = blk >> 6;
    const int ch  = blk & 63;
    const int n0  = ch * 16;

    const int nt = tid & 7;               // column pair: cols nt, nt+8
    const int c0 = (tid >> 3) * 2;        // channel pair

    float* Xs = sm + OFF_XT;
    float* Ys = sm + OFF_YS;
    float* Ss = sm + OFF_SS;

    // Learn this launch's epoch from our OWN slot (only we ever write it).
    if (tid == 0) sEpoch = g_arrive[blk];

    // ---- Stage all 4 weight matrices (padded rows) + X chunk ---------------
    {
        const float* srcs[4] = {wk, wv, wq, wp};
        #pragma unroll
        for (int i = 0; i < 16; i++) {
            const int e  = tid + NTHR * i;
            const int m  = i >> 2;
            const int e2 = e & 1023;
            const int r  = e2 >> 4, c4 = e2 & 15;
            float4 v = ((const float4*)srcs[m])[e2];
            *(float4*)&sm[m * 64 * WS + r * WS + c4 * 4] = v;
        }
        const float* xb = x + b * 65536 + n0;
        #pragma unroll
        for (int i = 0; i < 4; i++) {
            const int e = tid + NTHR * i;
            Xs[(e & 15) * XS + (e >> 4)] = xb[(e >> 4) * 1024 + (e & 15)];
        }
    }
    __syncthreads();
    const unsigned e1 = sEpoch + 1;       // this launch's arrival value

    // ---- Fused K/V/Q projections (packed f32x2 along j) --------------------
    {
        const ulonglong2* Wk0 = (const ulonglong2*)&sm[OFF_WK + c0 * WS];
        const ulonglong2* Wk1 = (const ulonglong2*)&sm[OFF_WK + (c0 + 1) * WS];
        const ulonglong2* Wv0 = (const ulonglong2*)&sm[OFF_WV + c0 * WS];
        const ulonglong2* Wv1 = (const ulonglong2*)&sm[OFF_WV + (c0 + 1) * WS];
        const ulonglong2* Wq0 = (const ulonglong2*)&sm[OFF_WQ + c0 * WS];
        const ulonglong2* Wq1 = (const ulonglong2*)&sm[OFF_WQ + (c0 + 1) * WS];
        const ulonglong2* X0  = (const ulonglong2*)&Xs[nt * XS];
        const ulonglong2* X1  = (const ulonglong2*)&Xs[(nt + 8) * XS];

        u64 K00 = 0, K01 = 0, K10 = 0, K11 = 0;
        u64 V00 = 0, V01 = 0, V10 = 0, V11 = 0;
        u64 Q00 = 0, Q01 = 0, Q10 = 0, Q11 = 0;

        #pragma unroll
        for (int jg = 0; jg < 16; jg++) {
            ulonglong2 xa = X0[jg], xb2 = X1[jg];
            ulonglong2 w;
            w = Wk0[jg];
            fma2(K00, w.x, xa.x);  fma2(K00, w.y, xa.y);
            fma2(K01, w.x, xb2.x); fma2(K01, w.y, xb2.y);
            w = Wk1[jg];
            fma2(K10, w.x, xa.x);  fma2(K10, w.y, xa.y);
            fma2(K11, w.x, xb2.x); fma2(K11, w.y, xb2.y);
            w = Wv0[jg];
            fma2(V00, w.x, xa.x);  fma2(V00, w.y, xa.y);
            fma2(V01, w.x, xb2.x); fma2(V01, w.y, xb2.y);
            w = Wv1[jg];
            fma2(V10, w.x, xa.x);  fma2(V10, w.y, xa.y);
            fma2(V11, w.x, xb2.x); fma2(V11, w.y, xb2.y);
            w = Wq0[jg];
            fma2(Q00, w.x, xa.x);  fma2(Q00, w.y, xa.y);
            fma2(Q01, w.x, xb2.x); fma2(Q01, w.y, xb2.y);
            w = Wq1[jg];
            fma2(Q10, w.x, xa.x);  fma2(Q10, w.y, xa.y);
            fma2(Q11, w.x, xb2.x); fma2(Q11, w.y, xb2.y);
        }

        float k00 = hsum2(K00), k01 = hsum2(K01), k10 = hsum2(K10), k11 = hsum2(K11);
        float v00 = hsum2(V00), v01 = hsum2(V01), v10 = hsum2(V10), v11 = hsum2(V11);

        *(float2*)&Ys[nt * XS + c0]       = make_float2(hsum2(Q00), hsum2(Q10));
        *(float2*)&Ys[(nt + 8) * XS + c0] = make_float2(hsum2(Q01), hsum2(Q11));

        float s0 = k00 * v00 + k01 * v01;
        float s1 = k10 * v10 + k11 * v11;
        s0 += __shfl_down_sync(0xffffffffu, s0, 4, 8);
        s1 += __shfl_down_sync(0xffffffffu, s1, 4, 8);
        s0 += __shfl_down_sync(0xffffffffu, s0, 2, 8);
        s1 += __shfl_down_sync(0xffffffffu, s1, 2, 8);
        s0 += __shfl_down_sync(0xffffffffu, s0, 1, 8);
        s1 += __shfl_down_sync(0xffffffffu, s1, 1, 8);
        if (nt == 0) {
            g_sPart[b][c0][ch]     = s0;
            g_sPart[b][c0 + 1][ch] = s1;
        }
    }

    // ---- Atomic-free, release-free grid barrier ----------------------------
    __syncthreads();                      // block-local: s-partials done
    if (tid == 0) {
        __threadfence();                  // publish this block's stores
        g_arrive[blk] = e1;               // parallel arrival (own slot)
    }
    if (tid < NBLK) {
        while (g_arrive[tid] != e1) { }   // observe ALL arrivals directly
        __threadfence();                  // acquire before cross-block reads
    }
    __syncthreads();

    // ---- Reduce s (4 threads/channel, fixed order -> deterministic) --------
    {
        const int c = tid >> 2, q = tid & 3;
        const float4* sp = (const float4*)&g_sPart[b][c][q * 16];
        float v = 0.f;
        #pragma unroll
        for (int j = 0; j < 4; j++) {
            float4 s4 = __ldcg(&sp[j]);
            v += s4.x + s4.y + s4.z + s4.w;
        }
        v += __shfl_down_sync(0xffffffffu, v, 2, 4);
        v += __shfl_down_sync(0xffffffffu, v, 1, 4);
        if (q == 0) Ss[c] = v;
    }
    __syncthreads();

    // ---- out = Wp · (s ∘ Ys) + X  (packed f32x2) ---------------------------
    {
        const ulonglong2* Wp0 = (const ulonglong2*)&sm[OFF_WP + c0 * WS];
        const ulonglong2* Wp1 = (const ulonglong2*)&sm[OFF_WP + (c0 + 1) * WS];
        const ulonglong2* Y0  = (const ulonglong2*)&Ys[nt * XS];
        const ulonglong2* Y1  = (const ulonglong2*)&Ys[(nt + 8) * XS];
        const ulonglong2* S2  = (const ulonglong2*)Ss;

        u64 O00 = 0, O01 = 0, O10 = 0, O11 = 0;
        #pragma unroll
        for (int jg = 0; jg < 16; jg++) {
            ulonglong2 ss = S2[jg];
            ulonglong2 y0 = Y0[jg], y1 = Y1[jg];
            y0.x = mul2(y0.x, ss.x); y0.y = mul2(y0.y, ss.y);
            y1.x = mul2(y1.x, ss.x); y1.y = mul2(y1.y, ss.y);
            ulonglong2 w;
            w = Wp0[jg];
            fma2(O00, w.x, y0.x); fma2(O00, w.y, y0.y);
            fma2(O01, w.x, y1.x); fma2(O01, w.y, y1.y);
            w = Wp1[jg];
            fma2(O10, w.x, y0.x); fma2(O10, w.y, y0.y);
            fma2(O11, w.x, y1.x); fma2(O11, w.y, y1.y);
        }
        float* ob = out + b * 65536 + n0;
        ob[c0 * 1024 + nt]           = hsum2(O00) + Xs[nt * XS + c0];
        ob[c0 * 1024 + nt + 8]       = hsum2(O01) + Xs[(nt + 8) * XS + c0];
        ob[(c0 + 1) * 1024 + nt]     = hsum2(O10) + Xs[nt * XS + c0 + 1];
        ob[(c0 + 1) * 1024 + nt + 8] = hsum2(O11) + Xs[(nt + 8) * XS + c0 + 1];
    }
}

extern "C" void kernel_launch(void* const* d_in, const int* in_sizes, int n_in,
                              void* d_out, int out_size) {
    const float* x  = (const float*)d_in[0];
    const float* wq = (const float*)d_in[1];
    const float* wk = (const float*)d_in[2];
    const float* wv = (const float*)d_in[3];
    const float* wp = (const float*)d_in[4];

    static int smem_set = 0;
    if (!smem_set) {
        cudaFuncSetAttribute(attn_fused, cudaFuncAttributeMaxDynamicSharedMemorySize,
                             SMEM_FLOATS * (int)sizeof(float));
        smem_set = 1;
    }
    attn_fused<<<NBLK, NTHR, SMEM_FLOATS * sizeof(float)>>>(
        x, wq, wk, wv, wp, (float*)d_out);
}

// round 17
// speedup vs baseline: 1.3617x; 1.3617x over previous
#include <cuda_runtime.h>

// out_b = Wp (s_b ∘ (Wq X_b)) + X_b,  s_b[c] = sum_n (Wk X_b)[c,n]*(Wv X_b)[c,n]
// B=2, C=64, N=1024. 128 blocks x 256 threads, one wave, ONE grid barrier.
// Thread tile: 2 channels x 2 columns. Packed fma.rn.f32x2 inner products.
// Barrier: atomic-free. Each block STORES an epoch to its own slot (parallel),
// block 0's threads poll the 128 slots in parallel, then ONE release store
// that all other blocks spin on (single L2 line, broadcast-friendly).

#define NBLK 128
#define NTHR 256
#define WS 68
#define XS 68

#define OFF_WK 0
#define OFF_WV (64 * WS)
#define OFF_WQ (2 * 64 * WS)
#define OFF_WP (3 * 64 * WS)
#define OFF_XT (4 * 64 * WS)
#define OFF_YS (OFF_XT + 16 * XS)
#define OFF_SS (OFF_YS + 16 * XS)
#define SMEM_FLOATS (OFF_SS + 64)

typedef unsigned long long u64;

__device__ float g_sPart[2][64][64];

// Atomic-free barrier state: monotonic epoch + per-block arrival slots.
__device__ volatile unsigned g_arrive[NBLK];
__device__ volatile unsigned g_epoch;

__device__ __forceinline__ void fma2(u64& d, u64 a, u64 b) {
    asm("fma.rn.f32x2 %0, %1, %2, %0;" : "+l"(d) : "l"(a), "l"(b));
}
__device__ __forceinline__ u64 mul2(u64 a, u64 b) {
    u64 d;
    asm("mul.rn.f32x2 %0, %1, %2;" : "=l"(d) : "l"(a), "l"(b));
    return d;
}
__device__ __forceinline__ float hsum2(u64 v) {
    float lo, hi;
    asm("mov.b64 {%0, %1}, %2;" : "=f"(lo), "=f"(hi) : "l"(v));
    return lo + hi;
}

extern __shared__ float sm[];

__global__ void __launch_bounds__(NTHR) attn_fused(
    const float* __restrict__ x,
    const float* __restrict__ wq, const float* __restrict__ wk,
    const float* __restrict__ wv, const float* __restrict__ wp,
    float* __restrict__ out)
{
    __shared__ unsigned sEpoch;

    const int tid = threadIdx.x;
    const int blk = blockIdx.x;
    const int b   = blk >> 6;
    const int ch  = blk & 63;
    const int n0  = ch * 16;

    const int nt = tid & 7;               // column pair: cols nt, nt+8
    const int c0 = (tid >> 3) * 2;        // channel pair

    float* Xs = sm + OFF_XT;
    float* Ys = sm + OFF_YS;
    float* Ss = sm + OFF_SS;

    // Capture launch epoch early (stable for the whole launch: release only
    // happens after every block arrives, and all blocks are co-resident).
    if (tid == 0) sEpoch = g_epoch;

    // ---- Stage all 4 weight matrices (padded rows) + X chunk ---------------
    {
        const float* srcs[4] = {wk, wv, wq, wp};
        #pragma unroll
        for (int i = 0; i < 16; i++) {
            const int e  = tid + NTHR * i;
            const int m  = i >> 2;
            const int e2 = e & 1023;
            const int r  = e2 >> 4, c4 = e2 & 15;
            float4 v = ((const float4*)srcs[m])[e2];
            *(float4*)&sm[m * 64 * WS + r * WS + c4 * 4] = v;
        }
        const float* xb = x + b * 65536 + n0;
        #pragma unroll
        for (int i = 0; i < 4; i++) {
            const int e = tid + NTHR * i;
            Xs[(e & 15) * XS + (e >> 4)] = xb[(e >> 4) * 1024 + (e & 15)];
        }
    }
    __syncthreads();
    const unsigned e1 = sEpoch + 1;       // this launch's arrival value

    // ---- Fused K/V/Q projections (packed f32x2 along j) --------------------
    {
        const ulonglong2* Wk0 = (const ulonglong2*)&sm[OFF_WK + c0 * WS];
        const ulonglong2* Wk1 = (const ulonglong2*)&sm[OFF_WK + (c0 + 1) * WS];
        const ulonglong2* Wv0 = (const ulonglong2*)&sm[OFF_WV + c0 * WS];
        const ulonglong2* Wv1 = (const ulonglong2*)&sm[OFF_WV + (c0 + 1) * WS];
        const ulonglong2* Wq0 = (const ulonglong2*)&sm[OFF_WQ + c0 * WS];
        const ulonglong2* Wq1 = (const ulonglong2*)&sm[OFF_WQ + (c0 + 1) * WS];
        const ulonglong2* X0  = (const ulonglong2*)&Xs[nt * XS];
        const ulonglong2* X1  = (const ulonglong2*)&Xs[(nt + 8) * XS];

        u64 K00 = 0, K01 = 0, K10 = 0, K11 = 0;
        u64 V00 = 0, V01 = 0, V10 = 0, V11 = 0;
        u64 Q00 = 0, Q01 = 0, Q10 = 0, Q11 = 0;

        #pragma unroll
        for (int jg = 0; jg < 16; jg++) {
            ulonglong2 xa = X0[jg], xb2 = X1[jg];
            ulonglong2 w;
            w = Wk0[jg];
            fma2(K00, w.x, xa.x);  fma2(K00, w.y, xa.y);
            fma2(K01, w.x, xb2.x); fma2(K01, w.y, xb2.y);
            w = Wk1[jg];
            fma2(K10, w.x, xa.x);  fma2(K10, w.y, xa.y);
            fma2(K11, w.x, xb2.x); fma2(K11, w.y, xb2.y);
            w = Wv0[jg];
            fma2(V00, w.x, xa.x);  fma2(V00, w.y, xa.y);
            fma2(V01, w.x, xb2.x); fma2(V01, w.y, xb2.y);
            w = Wv1[jg];
            fma2(V10, w.x, xa.x);  fma2(V10, w.y, xa.y);
            fma2(V11, w.x, xb2.x); fma2(V11, w.y, xb2.y);
            w = Wq0[jg];
            fma2(Q00, w.x, xa.x);  fma2(Q00, w.y, xa.y);
            fma2(Q01, w.x, xb2.x); fma2(Q01, w.y, xb2.y);
            w = Wq1[jg];
            fma2(Q10, w.x, xa.x);  fma2(Q10, w.y, xa.y);
            fma2(Q11, w.x, xb2.x); fma2(Q11, w.y, xb2.y);
        }

        float k00 = hsum2(K00), k01 = hsum2(K01), k10 = hsum2(K10), k11 = hsum2(K11);
        float v00 = hsum2(V00), v01 = hsum2(V01), v10 = hsum2(V10), v11 = hsum2(V11);

        *(float2*)&Ys[nt * XS + c0]       = make_float2(hsum2(Q00), hsum2(Q10));
        *(float2*)&Ys[(nt + 8) * XS + c0] = make_float2(hsum2(Q01), hsum2(Q11));

        float s0 = k00 * v00 + k01 * v01;
        float s1 = k10 * v10 + k11 * v11;
        s0 += __shfl_down_sync(0xffffffffu, s0, 4, 8);
        s1 += __shfl_down_sync(0xffffffffu, s1, 4, 8);
        s0 += __shfl_down_sync(0xffffffffu, s0, 2, 8);
        s1 += __shfl_down_sync(0xffffffffu, s1, 2, 8);
        s0 += __shfl_down_sync(0xffffffffu, s0, 1, 8);
        s1 += __shfl_down_sync(0xffffffffu, s1, 1, 8);
        if (nt == 0) {
            g_sPart[b][c0][ch]     = s0;
            g_sPart[b][c0 + 1][ch] = s1;
        }
    }

    // ---- Atomic-free grid barrier ------------------------------------------
    __syncthreads();                      // block-local: s-partials done
    if (tid == 0) {
        __threadfence();                  // publish this block's stores
        g_arrive[blk] = e1;               // parallel arrival (own slot)
    }
    if (blk == 0) {
        if (tid < NBLK) {
            while (g_arrive[tid] != e1) { }
        }
        __syncthreads();                  // all 128 slots observed
        if (tid == 0) {
            __threadfence();
            g_epoch = e1;                 // release
        }
        __syncthreads();
    } else {
        if (tid == 0) {
            while (g_epoch != e1) { }
            __threadfence();              // acquire
        }
        __syncthreads();
    }

    // ---- Reduce s (4 threads/channel, fixed order -> deterministic) --------
    {
        const int c = tid >> 2, q = tid & 3;
        const float4* sp = (const float4*)&g_sPart[b][c][q * 16];
        float v = 0.f;
        #pragma unroll
        for (int j = 0; j < 4; j++) {
            float4 s4 = __ldcg(&sp[j]);
            v += s4.x + s4.y + s4.z + s4.w;
        }
        v += __shfl_down_sync(0xffffffffu, v, 2, 4);
        v += __shfl_down_sync(0xffffffffu, v, 1, 4);
        if (q == 0) Ss[c] = v;
    }
    __syncthreads();

    // ---- out = Wp · (s ∘ Ys) + X  (packed f32x2) ---------------------------
    {
        const ulonglong2* Wp0 = (const ulonglong2*)&sm[OFF_WP + c0 * WS];
        const ulonglong2* Wp1 = (const ulonglong2*)&sm[OFF_WP + (c0 + 1) * WS];
        const ulonglong2* Y0  = (const ulonglong2*)&Ys[nt * XS];
        const ulonglong2* Y1  = (const ulonglong2*)&Ys[(nt + 8) * XS];
        const ulonglong2* S2  = (const ulonglong2*)Ss;

        u64 O00 = 0, O01 = 0, O10 = 0, O11 = 0;
        #pragma unroll
        for (int jg = 0; jg < 16; jg++) {
            ulonglong2 ss = S2[jg];
            ulonglong2 y0 = Y0[jg], y1 = Y1[jg];
            y0.x = mul2(y0.x, ss.x); y0.y = mul2(y0.y, ss.y);
            y1.x = mul2(y1.x, ss.x); y1.y = mul2(y1.y, ss.y);
            ulonglong2 w;
            w = Wp0[jg];
            fma2(O00, w.x, y0.x); fma2(O00, w.y, y0.y);
            fma2(O01, w.x, y1.x); fma2(O01, w.y, y1.y);
            w = Wp1[jg];
            fma2(O10, w.x, y0.x); fma2(O10, w.y, y0.y);
            fma2(O11, w.x, y1.x); fma2(O11, w.y, y1.y);
        }
        float* ob = out + b * 65536 + n0;
        ob[c0 * 1024 + nt]           = hsum2(O00) + Xs[nt * XS + c0];
        ob[c0 * 1024 + nt + 8]       = hsum2(O01) + Xs[(nt + 8) * XS + c0];
        ob[(c0 + 1) * 1024 + nt]     = hsum2(O10) + Xs[nt * XS + c0 + 1];
        ob[(c0 + 1) * 1024 + nt + 8] = hsum2(O11) + Xs[(nt + 8) * XS + c0 + 1];
    }
}

extern "C" void kernel_launch(void* const* d_in, const int* in_sizes, int n_in,
                              void* d_out, int out_size) {
    const float* x  = (const float*)d_in[0];
    const float* wq = (const float*)d_in[1];
    const float* wk = (const float*)d_in[2];
    const float* wv = (const float*)d_in[3];
    const float* wp = (const float*)d_in[4];

    static int smem_set = 0;
    if (!smem_set) {
        cudaFuncSetAttribute(attn_fused, cudaFuncAttributeMaxDynamicSharedMemorySize,
                             SMEM_FLOATS * (int)sizeof(float));
        smem_set = 1;
    }
    attn_fused<<<NBLK, NTHR, SMEM_FLOATS * sizeof(float)>>>(
        x, wq, wk, wv, wp, (float*)d_out);
}